// round 5
// baseline (speedup 1.0000x reference)
#include <cuda_runtime.h>
#include <cstdint>
#include <cstddef>

// LSTM encoder: B=128, T=2048, I=64, H=128
// out[0 : B*H) = h_last ; out[B*H : ...) = encoded [B,T,H]
constexpr int B = 128;
constexpr int T = 2048;
constexpr int I = 64;
constexpr int H = 128;
constexpr int G = 4 * H;              // 512 gates
constexpr int KREG = 112;             // W_hh k-values in registers per gate
constexpr int NP   = KREG / 2;        // 56 f32x2 pairs per gate
constexpr int NQR  = KREG / 4;        // 28 register h-quads
constexpr int NQ_SM = (H - KREG) / 4; // 4 smem h-quads (16 k-values)

__device__ float g_xp[(size_t)B * T * G + 2 * G];   // padded for overread

__device__ __forceinline__ void fma2(unsigned long long& d,
                                     unsigned long long a,
                                     unsigned long long b) {
    asm("fma.rn.f32x2 %0, %1, %2, %0;" : "+l"(d) : "l"(a), "l"(b));
}
__device__ __forceinline__ float pair_sum(unsigned long long v) {
    return __uint_as_float((unsigned)v) + __uint_as_float((unsigned)(v >> 32));
}
__device__ __forceinline__ float sig_f(float x) {
    return __fdividef(1.f, 1.f + __expf(-x));
}
__device__ __forceinline__ float tanh_f(float x) {
    return 1.f - 2.f * __fdividef(1.f, 1.f + __expf(2.f * x));
}

// ---------------------------------------------------------------------------
// x_proj: 1 gate per thread, 2 CTAs/SM (16 warps) to hide latency.
// grid = (BT/32, 2): blockIdx.x = 32-row block, blockIdx.y = gate half.
// ---------------------------------------------------------------------------
__global__ void __launch_bounds__(256, 2) xproj_kernel(
    const float* __restrict__ in,     // [B*T, I]
    const float* __restrict__ Wih,    // [G, I]
    const float* __restrict__ bih,
    const float* __restrict__ bhh)
{
    __shared__ float in_s[32 * I];    // 8 KB
    const int t = threadIdx.x;
    const size_t row0 = (size_t)blockIdx.x * 32;
    const int g = blockIdx.y * 256 + t;

    {   // load 32x64 input tile: 512 float4 by 256 threads
        const float4* src = (const float4*)(in + row0 * I);
        float4* dst = (float4*)in_s;
        dst[t]       = src[t];
        dst[t + 256] = src[t + 256];
    }

    unsigned long long w[32];
    {
        const unsigned long long* wr =
            (const unsigned long long*)(Wih + (size_t)g * I);
#pragma unroll
        for (int i = 0; i < 32; i++) w[i] = wr[i];
    }
    const float bias = bih[g] + bhh[g];
    __syncthreads();

    float* outp = g_xp + row0 * G + g;
#pragma unroll 4
    for (int r = 0; r < 32; r++) {
        const ulonglong2* ip = (const ulonglong2*)(in_s + r * I);
        unsigned long long a0 = 0ull, a1 = 0ull;
#pragma unroll
        for (int q = 0; q < 16; q++) {
            ulonglong2 iv = ip[q];
            fma2(a0, w[2 * q],     iv.x);
            fma2(a1, w[2 * q + 1], iv.y);
        }
        outp[(size_t)r * G] = pair_sum(a0) + pair_sum(a1) + bias;
    }
}

// ---------------------------------------------------------------------------
// Recurrence: 1 CTA/batch row, 256 threads.
// Half A (tid<128, j=tid): rows j (i) and j+128 (f); owns c_j, does update.
// Half B (j=tid-128):      rows j+256 (g) and j+384 (o); sends (tanh g, sig o).
// One-way exchange: B bar.arrive(1) -> A bar.sync(1); full bar 0 after h write.
// ---------------------------------------------------------------------------
__global__ void __launch_bounds__(256, 1) lstm_kernel(
    const float* __restrict__ h0,
    const float* __restrict__ c0,
    const float* __restrict__ Whh,
    float* __restrict__ out)
{
    extern __shared__ float smem[];
    ulonglong2* Ws2  = (ulonglong2*)smem;            // [NQ_SM][G] quads, 32 KB
    float*      h_s  = smem + NQ_SM * G * 4;         // 128 floats
    float2*     ex_s = (float2*)(h_s + H);           // 128 float2

    const int tid  = threadIdx.x;
    const int half = tid >> 7;
    const int j    = tid & 127;
    const int g0   = (half << 8) + j;    // i (A) / g (B)
    const int g1   = g0 + 128;           // f (A) / o (B)
    const int b    = blockIdx.x;

    // branchless activation constants: A sigmoid, B tanh
    const float aa = half ? -2.f : 1.f;
    const float bb = half ?  2.f : -1.f;
    const float cc = half ?  1.f : 0.f;

    {   // smem weight slice, k in [KREG,128)
        const ulonglong2* r0 = (const ulonglong2*)(Whh + (size_t)g0 * H + KREG);
        const ulonglong2* r1 = (const ulonglong2*)(Whh + (size_t)g1 * H + KREG);
#pragma unroll
        for (int q = 0; q < NQ_SM; q++) {
            Ws2[q * G + g0] = r0[q];
            Ws2[q * G + g1] = r1[q];
        }
    }

    unsigned long long w0[NP], w1[NP];
    {
        const unsigned long long* r0 = (const unsigned long long*)(Whh + (size_t)g0 * H);
        const unsigned long long* r1 = (const unsigned long long*)(Whh + (size_t)g1 * H);
#pragma unroll
        for (int i = 0; i < NP; i++) { w0[i] = r0[i]; w1[i] = r1[i]; }
    }

    float c = 0.f, hn_last = 0.f;
    if (half == 0) {
        c = c0[b * H + j];
        h_s[j] = h0[b * H + j];
    }

    const float* xp = g_xp + (size_t)b * T * G + g0;  // g1 stream = +128
    float xc0 = xp[0], xc1 = xp[128];
    xp += G;

    __syncthreads();

    float* enc = out + (size_t)B * H + (size_t)b * T * H;

    for (int t = 0; t < T; t++) {
        // prefetch next step's x (distance-1)
        float xn0 = xp[0], xn1 = xp[128];
        xp += G;

        unsigned long long a0 = 0ull, a1 = 0ull, b0 = 0ull, b1 = 0ull;
        const ulonglong2* h2 = (const ulonglong2*)h_s;

#pragma unroll
        for (int q = 0; q < NQR; q++) {               // k in [0,112)
            ulonglong2 hv = h2[q];
            fma2(a0, w0[2 * q],     hv.x);
            fma2(a1, w0[2 * q + 1], hv.y);
            fma2(b0, w1[2 * q],     hv.x);
            fma2(b1, w1[2 * q + 1], hv.y);
        }
#pragma unroll
        for (int q = 0; q < NQ_SM; q++) {             // k in [112,128)
            ulonglong2 hv = h2[NQR + q];
            ulonglong2 wa = Ws2[q * G + g0];
            ulonglong2 wb = Ws2[q * G + g1];
            fma2(a0, wa.x, hv.x);
            fma2(a1, wa.y, hv.y);
            fma2(b0, wb.x, hv.x);
            fma2(b1, wb.y, hv.y);
        }

        float p0 = pair_sum(a0) + pair_sum(a1) + xc0;
        float p1 = pair_sum(b0) + pair_sum(b1) + xc1;
        xc0 = xn0; xc1 = xn1;

        // A: v0 = sig(i), v1 = sig(f) ; B: v0 = tanh(g), v1 = sig(o)
        float v0 = fmaf(aa, __fdividef(1.f, 1.f + __expf(bb * p0)), cc);
        float v1 = sig_f(p1);

        if (half) {
            ex_s[j] = make_float2(v0, v1);
            asm volatile("bar.arrive 1, 256;" ::: "memory");   // non-blocking
        } else {
            asm volatile("bar.sync 1, 256;" ::: "memory");     // wait for B
            float2 go = ex_s[j];                  // (tanh g, sig o)
            c = v1 * c + v0 * go.x;               // sig(f)*c + sig(i)*tanh(g)
            float hn = go.y * tanh_f(c);
            h_s[j] = hn;
            enc[(size_t)t * H + j] = hn;
            hn_last = hn;
        }
        __syncthreads();                          // h_s ready for all
    }

    if (half == 0) out[b * H + j] = hn_last;
}

// ---------------------------------------------------------------------------
extern "C" void kernel_launch(void* const* d_in, const int* in_sizes, int n_in,
                              void* d_out, int out_size) {
    const float* input = (const float*)d_in[0];
    const float* h0    = (const float*)d_in[1];
    const float* c0    = (const float*)d_in[2];
    const float* Wih   = (const float*)d_in[3];
    const float* Whh   = (const float*)d_in[4];
    const float* bih   = (const float*)d_in[5];
    const float* bhh   = (const float*)d_in[6];
    float* out = (float*)d_out;

    constexpr int SMEM2 =
        (NQ_SM * G * 4 + H) * (int)sizeof(float) + H * (int)sizeof(float2);
    cudaFuncSetAttribute(lstm_kernel,
                         cudaFuncAttributeMaxDynamicSharedMemorySize, SMEM2);

    dim3 xgrid((B * T) / 32, 2);
    xproj_kernel<<<xgrid, 256>>>(input, Wih, bih, bhh);
    lstm_kernel<<<B, 256, SMEM2>>>(h0, c0, Whh, out);
}

// round 6
// speedup vs baseline: 1.3608x; 1.3608x over previous
#include <cuda_runtime.h>
#include <cstdint>
#include <cstddef>

// LSTM encoder: B=128, T=2048, I=64, H=128
// out[0 : B*H) = h_last ; out[B*H : ...) = encoded [B,T,H]
constexpr int B = 128;
constexpr int T = 2048;
constexpr int I = 64;
constexpr int H = 128;
constexpr int G = 4 * H;              // 512 gates
constexpr int KREG = 104;             // W_hh k-values in registers per gate
constexpr int NP   = KREG / 2;        // 52 f32x2 pairs per gate
constexpr int NQR  = KREG / 4;        // 26 register h-quads
constexpr int NQ_SM = (H - KREG) / 4; // 6 smem h-quads

__device__ float g_xp[(size_t)B * T * G + 2 * G];   // padded for overread

__device__ __forceinline__ void fma2(unsigned long long& d,
                                     unsigned long long a,
                                     unsigned long long b) {
    asm("fma.rn.f32x2 %0, %1, %2, %0;" : "+l"(d) : "l"(a), "l"(b));
}
__device__ __forceinline__ float pair_sum(unsigned long long v) {
    return __uint_as_float((unsigned)v) + __uint_as_float((unsigned)(v >> 32));
}
__device__ __forceinline__ float sig_f(float x) {
    return __fdividef(1.f, 1.f + __expf(-x));
}
__device__ __forceinline__ float tanh_f(float x) {
    return 1.f - 2.f * __fdividef(1.f, 1.f + __expf(2.f * x));
}
__device__ __forceinline__ void cpasync8(uint32_t smem_addr, const void* gptr) {
    asm volatile("cp.async.ca.shared.global [%0], [%1], 8;\n"
                 :: "r"(smem_addr), "l"(gptr) : "memory");
}

// ---------------------------------------------------------------------------
// x_proj: 128 threads, 2 gates/thread, 3 CTAs/SM (12 warps) for latency hiding.
// grid = (BT/32, 2): blockIdx.x = 32-row block, blockIdx.y = gate half.
// ---------------------------------------------------------------------------
__global__ void __launch_bounds__(128, 3) xproj_kernel(
    const float* __restrict__ in,     // [B*T, I]
    const float* __restrict__ Wih,    // [G, I]
    const float* __restrict__ bih,
    const float* __restrict__ bhh)
{
    __shared__ float in_s[32 * I];    // 8 KB
    const int t = threadIdx.x;        // 0..127
    const size_t row0 = (size_t)blockIdx.x * 32;
    const int gA = blockIdx.y * 256 + t;
    const int gB = gA + 128;

    {   // load 32x64 input tile: 512 float4 by 128 threads (4 each)
        const float4* src = (const float4*)(in + row0 * I);
        float4* dst = (float4*)in_s;
#pragma unroll
        for (int i = 0; i < 4; i++) dst[t + 128 * i] = src[t + 128 * i];
    }

    unsigned long long wA[32], wB[32];
    {
        const unsigned long long* ra = (const unsigned long long*)(Wih + (size_t)gA * I);
        const unsigned long long* rb = (const unsigned long long*)(Wih + (size_t)gB * I);
#pragma unroll
        for (int i = 0; i < 32; i++) { wA[i] = ra[i]; wB[i] = rb[i]; }
    }
    const float biasA = bih[gA] + bhh[gA];
    const float biasB = bih[gB] + bhh[gB];
    __syncthreads();

    float* outp = g_xp + row0 * G + gA;
#pragma unroll 2
    for (int r = 0; r < 32; r++) {
        const ulonglong2* ip = (const ulonglong2*)(in_s + r * I);
        unsigned long long a0 = 0ull, a1 = 0ull, b0 = 0ull, b1 = 0ull;
#pragma unroll
        for (int q = 0; q < 16; q++) {
            ulonglong2 iv = ip[q];
            fma2(a0, wA[2 * q],     iv.x);
            fma2(a1, wA[2 * q + 1], iv.y);
            fma2(b0, wB[2 * q],     iv.x);
            fma2(b1, wB[2 * q + 1], iv.y);
        }
        outp[(size_t)r * G]       = pair_sum(a0) + pair_sum(a1) + biasA;
        outp[(size_t)r * G + 128] = pair_sum(b0) + pair_sum(b1) + biasB;
    }
}

// ---------------------------------------------------------------------------
// Recurrence: 1 CTA/batch row, 256 threads. (R4 structure + cp.async x ring)
// Half A (tid<128, j=tid): rows j (i) and j+128 (f); owns c_j, does update.
// Half B (j=tid-128):      rows j+256 (g) and j+384 (o); sends (tanh g, sig o).
// x stream: 4-buffer smem ring, cp.async distance-2, waited before end barrier.
// ---------------------------------------------------------------------------
__global__ void __launch_bounds__(256, 1) lstm_kernel(
    const float* __restrict__ h0,
    const float* __restrict__ c0,
    const float* __restrict__ Whh,
    float* __restrict__ out)
{
    extern __shared__ float smem[];
    ulonglong2* Ws2  = (ulonglong2*)smem;              // [NQ_SM][G] quads, 48 KB
    float*      h_s  = smem + NQ_SM * G * 4;           // 128 floats
    float2*     ex_s = (float2*)(h_s + H);             // 128 float2
    float*      xb   = (float*)(ex_s + H);             // 4 * G floats (8 KB)

    const int tid  = threadIdx.x;
    const int half = tid >> 7;
    const int j    = tid & 127;
    const int g0   = (half << 8) + j;    // i (A) / g (B)
    const int g1   = g0 + 128;           // f (A) / o (B)
    const int b    = blockIdx.x;

    // branchless activation constants: A sigmoid, B tanh
    const float aa = half ? -2.f : 1.f;
    const float bb = half ?  2.f : -1.f;
    const float cc = half ?  1.f : 0.f;

    {   // smem weight slice, k in [KREG,128)
        const ulonglong2* r0 = (const ulonglong2*)(Whh + (size_t)g0 * H + KREG);
        const ulonglong2* r1 = (const ulonglong2*)(Whh + (size_t)g1 * H + KREG);
#pragma unroll
        for (int q = 0; q < NQ_SM; q++) {
            Ws2[q * G + g0] = r0[q];
            Ws2[q * G + g1] = r1[q];
        }
    }

    unsigned long long w0[NP], w1[NP];
    {
        const unsigned long long* r0 = (const unsigned long long*)(Whh + (size_t)g0 * H);
        const unsigned long long* r1 = (const unsigned long long*)(Whh + (size_t)g1 * H);
#pragma unroll
        for (int i = 0; i < NP; i++) { w0[i] = r0[i]; w1[i] = r1[i]; }
    }

    float c = 0.f, hn_last = 0.f;
    if (half == 0) {
        c = c0[b * H + j];
        h_s[j] = h0[b * H + j];
    }

    // x ring: each thread copies 8 B (2 floats) per step; thread covers
    // elements [2*tid, 2*tid+1] of the 512-gate row.
    const char* gx = (const char*)(g_xp + (size_t)b * T * G + tid * 2);
    const uint32_t xb_base = (uint32_t)__cvta_generic_to_shared(xb) + tid * 8u;

    // prologue: stage t=0 and t=1, wait both
    cpasync8(xb_base + 0 * G * 4, gx);  gx += (size_t)G * 4;
    asm volatile("cp.async.commit_group;\n" ::: "memory");
    cpasync8(xb_base + 1 * G * 4, gx);  gx += (size_t)G * 4;
    asm volatile("cp.async.commit_group;\n" ::: "memory");
    asm volatile("cp.async.wait_group 0;\n" ::: "memory");

    __syncthreads();    // publishes h_s, Ws2, and staged x

    float* enc = out + (size_t)B * H + (size_t)b * T * H;

    for (int t = 0; t < T; t++) {
        // stage x for t+2 (padded overread beyond T is safe)
        cpasync8(xb_base + ((t + 2) & 3) * G * 4, gx);
        gx += (size_t)G * 4;
        asm volatile("cp.async.commit_group;\n" ::: "memory");

        unsigned long long a0 = 0ull, a1 = 0ull, b0 = 0ull, b1 = 0ull;
        const ulonglong2* h2 = (const ulonglong2*)h_s;

#pragma unroll
        for (int q = 0; q < NQR; q++) {               // k in [0,104)
            ulonglong2 hv = h2[q];
            fma2(a0, w0[2 * q],     hv.x);
            fma2(a1, w0[2 * q + 1], hv.y);
            fma2(b0, w1[2 * q],     hv.x);
            fma2(b1, w1[2 * q + 1], hv.y);
        }
#pragma unroll
        for (int q = 0; q < NQ_SM; q++) {             // k in [104,128)
            ulonglong2 hv = h2[NQR + q];
            ulonglong2 wa = Ws2[q * G + g0];
            ulonglong2 wb = Ws2[q * G + g1];
            fma2(a0, wa.x, hv.x);
            fma2(a1, wa.y, hv.y);
            fma2(b0, wb.x, hv.x);
            fma2(b1, wb.y, hv.y);
        }

        const float* xrow = xb + (t & 3) * G;
        float p0 = pair_sum(a0) + pair_sum(a1) + xrow[g0];
        float p1 = pair_sum(b0) + pair_sum(b1) + xrow[g1];

        // A: v0 = sig(i), v1 = sig(f) ; B: v0 = tanh(g), v1 = sig(o)
        float v0 = fmaf(aa, __fdividef(1.f, 1.f + __expf(bb * p0)), cc);
        float v1 = sig_f(p1);

        if (half) ex_s[j] = make_float2(v0, v1);
        __syncthreads();

        if (!half) {
            float2 go = ex_s[j];                 // (tanh g, sig o)
            c = v1 * c + v0 * go.x;              // sig(f)*c + sig(i)*tanh(g)
            float hn = go.y * tanh_f(c);
            h_s[j] = hn;
            enc[(size_t)t * H + j] = hn;
            hn_last = hn;
        }

        // ensure x for t+1 (issued at t-1) has landed, then publish all
        asm volatile("cp.async.wait_group 1;\n" ::: "memory");
        __syncthreads();
    }

    if (half == 0) out[b * H + j] = hn_last;
}

// ---------------------------------------------------------------------------
extern "C" void kernel_launch(void* const* d_in, const int* in_sizes, int n_in,
                              void* d_out, int out_size) {
    const float* input = (const float*)d_in[0];
    const float* h0    = (const float*)d_in[1];
    const float* c0    = (const float*)d_in[2];
    const float* Wih   = (const float*)d_in[3];
    const float* Whh   = (const float*)d_in[4];
    const float* bih   = (const float*)d_in[5];
    const float* bhh   = (const float*)d_in[6];
    float* out = (float*)d_out;

    constexpr int SMEM2 = (NQ_SM * G * 4 + H) * (int)sizeof(float)
                        + H * (int)sizeof(float2)
                        + 4 * G * (int)sizeof(float);     // 58880 B
    cudaFuncSetAttribute(lstm_kernel,
                         cudaFuncAttributeMaxDynamicSharedMemorySize, SMEM2);

    dim3 xgrid((B * T) / 32, 2);
    xproj_kernel<<<xgrid, 128>>>(input, Wih, bih, bhh);
    lstm_kernel<<<B, 256, SMEM2>>>(h0, c0, Whh, out);
}

// round 8
// speedup vs baseline: 1.7160x; 1.2610x over previous
#include <cuda_runtime.h>
#include <cuda_bf16.h>
#include <cstdint>
#include <cstddef>

// LSTM encoder: B=128, T=2048, I=64, H=128
// out[0 : B*H) = h_last ; out[B*H : ...) = encoded [B,T,H]
constexpr int B = 128;
constexpr int T = 2048;
constexpr int I = 64;
constexpr int H = 128;
constexpr int G = 4 * H;              // 512 gates
constexpr int KREG = 104;             // W_hh k-values in registers per gate
constexpr int NP   = KREG / 2;        // 52 f32x2 pairs per gate
constexpr int NQR  = KREG / 4;        // 26 register h-quads
constexpr int NQ_SM = (H - KREG) / 4; // 6 smem h-quads

__device__ float g_xp[(size_t)B * T * G + 2 * G];   // padded for overread
__device__ __nv_bfloat16 g_whi[G * I];              // W_ih hi split
__device__ __nv_bfloat16 g_wlo[G * I];              // W_ih lo split

__device__ __forceinline__ void fma2(unsigned long long& d,
                                     unsigned long long a,
                                     unsigned long long b) {
    asm("fma.rn.f32x2 %0, %1, %2, %0;" : "+l"(d) : "l"(a), "l"(b));
}
__device__ __forceinline__ float pair_sum(unsigned long long v) {
    return __uint_as_float((unsigned)v) + __uint_as_float((unsigned)(v >> 32));
}
__device__ __forceinline__ float sig_f(float x) {
    return __fdividef(1.f, 1.f + __expf(-x));
}
__device__ __forceinline__ float tanh_f(float x) {
    return 1.f - 2.f * __fdividef(1.f, 1.f + __expf(2.f * x));
}
__device__ __forceinline__ void cpasync8(uint32_t smem_addr, const void* gptr) {
    asm volatile("cp.async.ca.shared.global [%0], [%1], 8;\n"
                 :: "r"(smem_addr), "l"(gptr) : "memory");
}
__device__ __forceinline__ uint32_t sw128(uint32_t off) {
    return off ^ ((off >> 3) & 0x70);
}
__device__ __forceinline__ void ldsm_x4(uint32_t* r, uint32_t addr) {
    asm volatile("ldmatrix.sync.aligned.m8n8.x4.shared.b16 {%0,%1,%2,%3}, [%4];"
                 : "=r"(r[0]), "=r"(r[1]), "=r"(r[2]), "=r"(r[3]) : "r"(addr));
}
__device__ __forceinline__ void ldsm_x2(uint32_t* r, uint32_t addr) {
    asm volatile("ldmatrix.sync.aligned.m8n8.x2.shared.b16 {%0,%1}, [%2];"
                 : "=r"(r[0]), "=r"(r[1]) : "r"(addr));
}
__device__ __forceinline__ void mma_bf16(float* c, const uint32_t* a,
                                         const uint32_t* b) {
    asm volatile(
        "mma.sync.aligned.m16n8k16.row.col.f32.bf16.bf16.f32 "
        "{%0,%1,%2,%3}, {%4,%5,%6,%7}, {%8,%9}, {%0,%1,%2,%3};"
        : "+f"(c[0]), "+f"(c[1]), "+f"(c[2]), "+f"(c[3])
        : "r"(a[0]), "r"(a[1]), "r"(a[2]), "r"(a[3]), "r"(b[0]), "r"(b[1]));
}

// ---------------------------------------------------------------------------
// Prep: split W_ih into bf16 hi/lo.
// ---------------------------------------------------------------------------
__global__ void wsplit_kernel(const float* __restrict__ Wih) {
    int i = blockIdx.x * blockDim.x + threadIdx.x;   // 32768 total
    float w = Wih[i];
    __nv_bfloat16 h = __float2bfloat16_rn(w);
    g_whi[i] = h;
    g_wlo[i] = __float2bfloat16_rn(w - __bfloat162float(h));
}

// ---------------------------------------------------------------------------
// x_proj via mma.sync (HMMA, bf16 split): per CTA D[64, 512] = A(64x64) W^T.
// 3 passes: Ahi*Bhi + Ahi*Blo + Alo*Bhi, fp32 accumulators.
// 8 warps = 2(M) x 4(N); warp tile 32x128 = 2 m-tiles x 16 n-tiles.
// ---------------------------------------------------------------------------
constexpr int SM_BIAS = 0;            // 512 floats (2 KB)
constexpr int SM_AHI  = 2048;         // 64 rows x 128B = 8 KB (SW128)
constexpr int SM_ALO  = 10240;        // 8 KB
constexpr int SM_BHI  = 18432;        // 512 rows x 128B = 64 KB
constexpr int SM_BLO  = 83968;        // 64 KB
constexpr int SMEM_TC = 149504;       // 146 KB

__global__ void __launch_bounds__(256, 1) xproj_tc_kernel(
    const float* __restrict__ in,
    const float* __restrict__ bih,
    const float* __restrict__ bhh)
{
    extern __shared__ char sm[];
    const int t    = threadIdx.x;
    const int lane = t & 31;
    const int wid  = t >> 5;
    const uint32_t smb = (uint32_t)__cvta_generic_to_shared(sm);
    const size_t m0 = (size_t)blockIdx.x * 64;
    float* bias_s = (float*)(sm + SM_BIAS);

    // A tile: 64 rows x 64 fp32 -> bf16 hi/lo, SW128. Thread: row t/4, quarter t&3.
    {
        const int row = t >> 2, q = t & 3;
        const float4* src = (const float4*)(in + (m0 + row) * I + q * 16);
#pragma unroll
        for (int i = 0; i < 4; i++) {
            float4 v = src[i];
            __nv_bfloat16 h0 = __float2bfloat16_rn(v.x);
            __nv_bfloat16 h1 = __float2bfloat16_rn(v.y);
            __nv_bfloat16 h2 = __float2bfloat16_rn(v.z);
            __nv_bfloat16 h3 = __float2bfloat16_rn(v.w);
            __nv_bfloat162 hp0, hp1, lp0, lp1;
            hp0.x = h0; hp0.y = h1; hp1.x = h2; hp1.y = h3;
            lp0.x = __float2bfloat16_rn(v.x - __bfloat162float(h0));
            lp0.y = __float2bfloat16_rn(v.y - __bfloat162float(h1));
            lp1.x = __float2bfloat16_rn(v.z - __bfloat162float(h2));
            lp1.y = __float2bfloat16_rn(v.w - __bfloat162float(h3));
            uint32_t b0 = row * 128 + q * 32 + i * 8;
            *(uint32_t*)(sm + SM_AHI + sw128(b0))     = *(uint32_t*)&hp0;
            *(uint32_t*)(sm + SM_AHI + sw128(b0 + 4)) = *(uint32_t*)&hp1;
            *(uint32_t*)(sm + SM_ALO + sw128(b0))     = *(uint32_t*)&lp0;
            *(uint32_t*)(sm + SM_ALO + sw128(b0 + 4)) = *(uint32_t*)&lp1;
        }
    }

    // W tiles: 512 rows x 64 bf16 (128B/row), SW128. uint4 = 16B chunks.
    {
        const uint4* shi = (const uint4*)g_whi;
        const uint4* slo = (const uint4*)g_wlo;
#pragma unroll
        for (int it = 0; it < 16; it++) {
            int u = t + it * 256;                 // 0..4095
            int row = u >> 3, ch = u & 7;
            uint32_t off = sw128(row * 128 + ch * 16);
            *(uint4*)(sm + SM_BHI + off) = shi[u];
            *(uint4*)(sm + SM_BLO + off) = slo[u];
        }
    }
    for (int u = t; u < G; u += 256) bias_s[u] = bih[u] + bhh[u];
    __syncthreads();

    // Warp tiling: 2(M) x 4(N)
    const int wm = wid >> 2;              // 0..1
    const int wn = wid & 3;               // 0..3
    const int mbase = wm * 32;
    const int nbase = wn * 128;

    float acc[2][16][4];
#pragma unroll
    for (int mt = 0; mt < 2; mt++)
#pragma unroll
        for (int nt = 0; nt < 16; nt++)
#pragma unroll
            for (int r = 0; r < 4; r++) acc[mt][nt][r] = 0.f;

    const uint32_t a_row = lane & 15;
    const uint32_t a_koff = (lane >> 4) << 4;             // 0 or 16 bytes
    const uint32_t b_row = lane & 7;
    const uint32_t b_koff = ((lane >> 3) & 1) << 4;       // 0 or 16 bytes

#pragma unroll
    for (int pass = 0; pass < 3; pass++) {
        const uint32_t Ab = smb + (pass == 2 ? SM_ALO : SM_AHI);
        const uint32_t Bb = smb + (pass == 1 ? SM_BLO : SM_BHI);
#pragma unroll
        for (int ks = 0; ks < 4; ks++) {
            uint32_t afr[2][4];
#pragma unroll
            for (int mt = 0; mt < 2; mt++) {
                uint32_t off = (mbase + mt * 16 + a_row) * 128 + ks * 32 + a_koff;
                ldsm_x4(afr[mt], Ab + sw128(off));
            }
#pragma unroll
            for (int nt = 0; nt < 16; nt++) {
                uint32_t boff = (nbase + nt * 8 + b_row) * 128 + ks * 32 + b_koff;
                uint32_t bfr[2];
                ldsm_x2(bfr, Bb + sw128(boff));
                mma_bf16(acc[0][nt], afr[0], bfr);
                mma_bf16(acc[1][nt], afr[1], bfr);
            }
        }
    }

    // Epilogue: c0,c1 -> row lane/4, cols 2*(lane%4); c2,c3 -> row+8.
    {
        const int r0 = lane >> 2;
        const int cq = 2 * (lane & 3);
#pragma unroll
        for (int mt = 0; mt < 2; mt++) {
            size_t row = m0 + mbase + mt * 16 + r0;
#pragma unroll
            for (int nt = 0; nt < 16; nt++) {
                int col = nbase + nt * 8 + cq;
                float b0 = bias_s[col], b1 = bias_s[col + 1];
                *(float2*)(g_xp + row * G + col) =
                    make_float2(acc[mt][nt][0] + b0, acc[mt][nt][1] + b1);
                *(float2*)(g_xp + (row + 8) * G + col) =
                    make_float2(acc[mt][nt][2] + b0, acc[mt][nt][3] + b1);
            }
        }
    }
}

// ---------------------------------------------------------------------------
// Recurrence (unchanged from R6): 1 CTA/batch row, 256 threads, cp.async x ring.
// ---------------------------------------------------------------------------
__global__ void __launch_bounds__(256, 1) lstm_kernel(
    const float* __restrict__ h0,
    const float* __restrict__ c0,
    const float* __restrict__ Whh,
    float* __restrict__ out)
{
    extern __shared__ float smem[];
    ulonglong2* Ws2  = (ulonglong2*)smem;              // [NQ_SM][G] quads, 48 KB
    float*      h_s  = smem + NQ_SM * G * 4;           // 128 floats
    float2*     ex_s = (float2*)(h_s + H);             // 128 float2
    float*      xb   = (float*)(ex_s + H);             // 4 * G floats (8 KB)

    const int tid  = threadIdx.x;
    const int half = tid >> 7;
    const int j    = tid & 127;
    const int g0   = (half << 8) + j;    // i (A) / g (B)
    const int g1   = g0 + 128;           // f (A) / o (B)
    const int b    = blockIdx.x;

    const float aa = half ? -2.f : 1.f;
    const float bb = half ?  2.f : -1.f;
    const float cc = half ?  1.f : 0.f;

    {
        const ulonglong2* r0 = (const ulonglong2*)(Whh + (size_t)g0 * H + KREG);
        const ulonglong2* r1 = (const ulonglong2*)(Whh + (size_t)g1 * H + KREG);
#pragma unroll
        for (int q = 0; q < NQ_SM; q++) {
            Ws2[q * G + g0] = r0[q];
            Ws2[q * G + g1] = r1[q];
        }
    }

    unsigned long long w0[NP], w1[NP];
    {
        const unsigned long long* r0 = (const unsigned long long*)(Whh + (size_t)g0 * H);
        const unsigned long long* r1 = (const unsigned long long*)(Whh + (size_t)g1 * H);
#pragma unroll
        for (int i = 0; i < NP; i++) { w0[i] = r0[i]; w1[i] = r1[i]; }
    }

    float c = 0.f, hn_last = 0.f;
    if (half == 0) {
        c = c0[b * H + j];
        h_s[j] = h0[b * H + j];
    }

    const char* gx = (const char*)(g_xp + (size_t)b * T * G + tid * 2);
    const uint32_t xb_base = (uint32_t)__cvta_generic_to_shared(xb) + tid * 8u;

    cpasync8(xb_base + 0 * G * 4, gx);  gx += (size_t)G * 4;
    asm volatile("cp.async.commit_group;\n" ::: "memory");
    cpasync8(xb_base + 1 * G * 4, gx);  gx += (size_t)G * 4;
    asm volatile("cp.async.commit_group;\n" ::: "memory");
    asm volatile("cp.async.wait_group 0;\n" ::: "memory");

    __syncthreads();

    float* enc = out + (size_t)B * H + (size_t)b * T * H;

    for (int t = 0; t < T; t++) {
        cpasync8(xb_base + ((t + 2) & 3) * G * 4, gx);
        gx += (size_t)G * 4;
        asm volatile("cp.async.commit_group;\n" ::: "memory");

        unsigned long long a0 = 0ull, a1 = 0ull, b0 = 0ull, b1 = 0ull;
        const ulonglong2* h2 = (const ulonglong2*)h_s;

#pragma unroll
        for (int q = 0; q < NQR; q++) {
            ulonglong2 hv = h2[q];
            fma2(a0, w0[2 * q],     hv.x);
            fma2(a1, w0[2 * q + 1], hv.y);
            fma2(b0, w1[2 * q],     hv.x);
            fma2(b1, w1[2 * q + 1], hv.y);
        }
#pragma unroll
        for (int q = 0; q < NQ_SM; q++) {
            ulonglong2 hv = h2[NQR + q];
            ulonglong2 wa = Ws2[q * G + g0];
            ulonglong2 wb = Ws2[q * G + g1];
            fma2(a0, wa.x, hv.x);
            fma2(a1, wa.y, hv.y);
            fma2(b0, wb.x, hv.x);
            fma2(b1, wb.y, hv.y);
        }

        const float* xrow = xb + (t & 3) * G;
        float p0 = pair_sum(a0) + pair_sum(a1) + xrow[g0];
        float p1 = pair_sum(b0) + pair_sum(b1) + xrow[g1];

        float v0 = fmaf(aa, __fdividef(1.f, 1.f + __expf(bb * p0)), cc);
        float v1 = sig_f(p1);

        if (half) ex_s[j] = make_float2(v0, v1);
        __syncthreads();

        if (!half) {
            float2 go = ex_s[j];
            c = v1 * c + v0 * go.x;
            float hn = go.y * tanh_f(c);
            h_s[j] = hn;
            enc[(size_t)t * H + j] = hn;
            hn_last = hn;
        }

        asm volatile("cp.async.wait_group 1;\n" ::: "memory");
        __syncthreads();
    }

    if (half == 0) out[b * H + j] = hn_last;
}

// ---------------------------------------------------------------------------
extern "C" void kernel_launch(void* const* d_in, const int* in_sizes, int n_in,
                              void* d_out, int out_size) {
    const float* input = (const float*)d_in[0];
    const float* h0    = (const float*)d_in[1];
    const float* c0    = (const float*)d_in[2];
    const float* Wih   = (const float*)d_in[3];
    const float* Whh   = (const float*)d_in[4];
    const float* bih   = (const float*)d_in[5];
    const float* bhh   = (const float*)d_in[6];
    float* out = (float*)d_out;

    constexpr int SMEM2 = (NQ_SM * G * 4 + H) * (int)sizeof(float)
                        + H * (int)sizeof(float2)
                        + 4 * G * (int)sizeof(float);
    cudaFuncSetAttribute(lstm_kernel,
                         cudaFuncAttributeMaxDynamicSharedMemorySize, SMEM2);
    cudaFuncSetAttribute(xproj_tc_kernel,
                         cudaFuncAttributeMaxDynamicSharedMemorySize, SMEM_TC);

    wsplit_kernel<<<(G * I) / 256, 256>>>(Wih);
    xproj_tc_kernel<<<(B * T) / 64, 256, SMEM_TC>>>(input, bih, bhh);
    lstm_kernel<<<B, 256, SMEM2>>>(h0, c0, Whh, out);
}